// round 2
// baseline (speedup 1.0000x reference)
#include <cuda_runtime.h>
#include <math.h>

#define NN 50000
#define EE 600000
#define NSTEPS 5

// ---------------- scratch (device globals: allocation-free) ----------------
// g_t: [NN,512] per-etype transformed feats; ALSO reused (a) as gh buffer
// [NN,384] after aggregate consumes it, (b) as GAT output [NN,256].
__device__ float g_t[(size_t)NN * 512];
__device__ float g_a[(size_t)NN * 128];     // aggregated messages
__device__ float g_gi[(size_t)NN * 384];
__device__ float g_h[(size_t)NN * 128];     // current hidden state
__device__ float g_zft[(size_t)NN * 256];   // GAT projection
__device__ float g_el[NN * 2];
__device__ float g_er[NN * 2];
__device__ float g_mx[NN * 2];
__device__ int   g_indptr[NN + 1];
__device__ int   g_cursor[NN + 1];
__device__ int   g_eids[EE];
__device__ int   g_goff[65];
__device__ float g_part[64 * 16 * 256];
__device__ float g_hg[64 * 256];
__device__ float g_logits[2 * 64 * 2 * 32];
__device__ float g_WcatB[128 * 512];        // W_et repacked: [d][k*128+o]
__device__ float g_WihB[128 * 384];         // W_ih^T
__device__ float g_WhhB[128 * 384];         // W_hh^T
__device__ float g_WfcB[128 * 256];         // W_fc^T
__device__ float g_zerobias[512];           // stays zero (bss)

__device__ __forceinline__ float sigf(float x) { return 1.0f / (1.0f + expf(-x)); }
__device__ __forceinline__ float leakyf(float x) { return x > 0.0f ? x : 0.2f * x; }

// ---------------- weight prepack ----------------
__global__ void prep_wet(const float* __restrict__ W) {
    int i = blockIdx.x * 256 + threadIdx.x;
    if (i >= 128 * 512) return;
    int d = i >> 9, col = i & 511;
    int k = col >> 7, o = col & 127;
    g_WcatB[i] = W[(k << 14) + (o << 7) + d];
}

__global__ void prep_tr(const float* __restrict__ W, float* __restrict__ out, int M) {
    int i = blockIdx.x * 256 + threadIdx.x;
    if (i >= 128 * M) return;
    int d = i / M, m = i - d * M;
    out[i] = W[m * 128 + d];
}

// ---------------- CSR build ----------------
__global__ void hist_kernel(const int* __restrict__ dst) {
    int i = blockIdx.x * 256 + threadIdx.x;
    if (i < EE) atomicAdd(&g_cursor[dst[i]], 1);
}

__global__ void scan_kernel() {
    __shared__ int sm[1024];
    int tid = threadIdx.x;
    const int n = NN;
    int chunk = (n + 1023) / 1024;
    int start = tid * chunk;
    int end = min(start + chunk, n);
    int s = 0;
    for (int i = start; i < end; i++) s += g_cursor[i];
    sm[tid] = s;
    __syncthreads();
    for (int off = 1; off < 1024; off <<= 1) {
        int v = (tid >= off) ? sm[tid - off] : 0;
        __syncthreads();
        sm[tid] += v;
        __syncthreads();
    }
    int run = (tid == 0) ? 0 : sm[tid - 1];
    for (int i = start; i < end; i++) {
        int c = g_cursor[i];
        g_indptr[i] = run;
        g_cursor[i] = run;   // cursor for scatter
        run += c;
    }
    if (tid == 1023) g_indptr[n] = run;
}

__global__ void scatter_kernel(const int* __restrict__ dst) {
    int i = blockIdx.x * 256 + threadIdx.x;
    if (i >= EE) return;
    int pos = atomicAdd(&g_cursor[dst[i]], 1);
    g_eids[pos] = i;
}

__global__ void goff_kernel(const int* __restrict__ gid) {
    int g = threadIdx.x;
    if (g > 64) return;
    int lo = 0, hi = NN;
    while (lo < hi) {
        int mid = (lo + hi) >> 1;
        if (gid[mid] < g) lo = mid + 1; else hi = mid;
    }
    g_goff[g] = lo;
}

// ---------------- fp32 SGEMM: C[NN,M] = A[NN,128] @ B[128,M] + bias ----------------
__global__ void __launch_bounds__(256) gemm128(
    const float* __restrict__ A, const float* __restrict__ B,
    const float* __restrict__ bias, float* __restrict__ C, int M)
{
    __shared__ float As[8][128];
    __shared__ float Bs[8][128];
    const int tid = threadIdx.x;
    const int brow = blockIdx.y << 7;
    const int bcol = blockIdx.x << 7;
    const int ty = tid >> 4;
    const int tx = tid & 15;
    float acc[8][8];
#pragma unroll
    for (int i = 0; i < 8; i++)
#pragma unroll
        for (int j = 0; j < 8; j++) acc[i][j] = 0.0f;

    const int arow = tid >> 1;
    const int acol = (tid & 1) << 2;
    const int bk   = tid >> 5;
    const int bc   = (tid & 31) << 2;

    for (int kk = 0; kk < 128; kk += 8) {
        float4 av = make_float4(0.f, 0.f, 0.f, 0.f);
        int gr = brow + arow;
        if (gr < NN) av = *(const float4*)(A + (size_t)gr * 128 + kk + acol);
        As[acol + 0][arow] = av.x;
        As[acol + 1][arow] = av.y;
        As[acol + 2][arow] = av.z;
        As[acol + 3][arow] = av.w;
        *(float4*)&Bs[bk][bc] = *(const float4*)(B + (size_t)(kk + bk) * M + bcol + bc);
        __syncthreads();
#pragma unroll
        for (int k = 0; k < 8; k++) {
            float4 a0 = *(float4*)&As[k][ty << 2];
            float4 a1 = *(float4*)&As[k][64 + (ty << 2)];
            float4 b0 = *(float4*)&Bs[k][tx << 2];
            float4 b1 = *(float4*)&Bs[k][64 + (tx << 2)];
            float ar_[8] = {a0.x, a0.y, a0.z, a0.w, a1.x, a1.y, a1.z, a1.w};
            float br_[8] = {b0.x, b0.y, b0.z, b0.w, b1.x, b1.y, b1.z, b1.w};
#pragma unroll
            for (int i = 0; i < 8; i++)
#pragma unroll
                for (int j = 0; j < 8; j++) acc[i][j] += ar_[i] * br_[j];
        }
        __syncthreads();
    }
#pragma unroll
    for (int i = 0; i < 8; i++) {
        int rloc = (i < 4) ? ((ty << 2) + i) : (64 + (ty << 2) + i - 4);
        int r = brow + rloc;
        if (r >= NN) continue;
#pragma unroll
        for (int jh = 0; jh < 2; jh++) {
            int cloc = jh * 64 + (tx << 2);
            int c0 = bcol + cloc;
            float4 o;
            o.x = acc[i][jh * 4 + 0] + bias[c0 + 0];
            o.y = acc[i][jh * 4 + 1] + bias[c0 + 1];
            o.z = acc[i][jh * 4 + 2] + bias[c0 + 2];
            o.w = acc[i][jh * 4 + 3] + bias[c0 + 3];
            *(float4*)(C + (size_t)r * M + c0) = o;
        }
    }
}

// ---------------- message aggregation: a[d] = sum over in-edges of t[etype,src] ----------------
__global__ void aggregate_kernel(const int* __restrict__ src, const int* __restrict__ et) {
    int w = (blockIdx.x * blockDim.x + threadIdx.x) >> 5;
    if (w >= NN) return;
    int lane = threadIdx.x & 31;
    int beg = g_indptr[w], end = g_indptr[w + 1];
    float4 acc = make_float4(0.f, 0.f, 0.f, 0.f);
    for (int i = beg; i < end; i++) {
        int e = g_eids[i];
        const float4 v = *(const float4*)(g_t + (size_t)src[e] * 512 + et[e] * 128 + lane * 4);
        acc.x += v.x; acc.y += v.y; acc.z += v.z; acc.w += v.w;
    }
    *(float4*)(g_a + (size_t)w * 128 + lane * 4) = acc;
}

// ---------------- GRU elementwise (gh lives in g_t, reused) ----------------
__global__ void gru_kernel() {
    int idx = blockIdx.x * 256 + threadIdx.x;
    if (idx >= NN * 128) return;
    int n = idx >> 7, d = idx & 127;
    const float* gi = g_gi + (size_t)n * 384;
    const float* gh = g_t + (size_t)n * 384;   // aliased into g_t
    float r = sigf(gi[d] + gh[d]);
    float z = sigf(gi[128 + d] + gh[128 + d]);
    float nn_ = tanhf(gi[256 + d] + r * gh[256 + d]);
    g_h[idx] = (1.0f - z) * nn_ + z * g_h[idx];
}

// ---------------- L2 normalize + sigmoid ----------------
__global__ void normsig_kernel() {
    int w = (blockIdx.x * blockDim.x + threadIdx.x) >> 5;
    if (w >= NN) return;
    int lane = threadIdx.x & 31;
    float4 v = *(float4*)(g_h + (size_t)w * 128 + lane * 4);
    float ss = v.x * v.x + v.y * v.y + v.z * v.z + v.w * v.w;
    for (int o = 16; o; o >>= 1) ss += __shfl_xor_sync(0xffffffff, ss, o);
    float inv = 1.0f / fmaxf(sqrtf(ss), 1e-12f);
    v.x = sigf(v.x * inv);
    v.y = sigf(v.y * inv);
    v.z = sigf(v.z * inv);
    v.w = sigf(v.w * inv);
    *(float4*)(g_h + (size_t)w * 128 + lane * 4) = v;
}

// ---------------- GAT: el/er per node ----------------
__global__ void elr_kernel(const float* __restrict__ al, const float* __restrict__ ar) {
    int w = (blockIdx.x * blockDim.x + threadIdx.x) >> 5;
    if (w >= NN) return;
    int lane = threadIdx.x & 31;
    float4 z0 = *(float4*)(g_zft + (size_t)w * 256 + lane * 4);
    float4 z1 = *(float4*)(g_zft + (size_t)w * 256 + 128 + lane * 4);
    float4 l0v = *(const float4*)(al + lane * 4);
    float4 l1v = *(const float4*)(al + 128 + lane * 4);
    float4 r0v = *(const float4*)(ar + lane * 4);
    float4 r1v = *(const float4*)(ar + 128 + lane * 4);
    float l0 = z0.x * l0v.x + z0.y * l0v.y + z0.z * l0v.z + z0.w * l0v.w;
    float l1 = z1.x * l1v.x + z1.y * l1v.y + z1.z * l1v.z + z1.w * l1v.w;
    float r0 = z0.x * r0v.x + z0.y * r0v.y + z0.z * r0v.z + z0.w * r0v.w;
    float r1 = z1.x * r1v.x + z1.y * r1v.y + z1.z * r1v.z + z1.w * r1v.w;
    for (int o = 16; o; o >>= 1) {
        l0 += __shfl_xor_sync(0xffffffff, l0, o);
        l1 += __shfl_xor_sync(0xffffffff, l1, o);
        r0 += __shfl_xor_sync(0xffffffff, r0, o);
        r1 += __shfl_xor_sync(0xffffffff, r1, o);
    }
    if (lane == 0) {
        g_el[w * 2 + 0] = l0; g_el[w * 2 + 1] = l1;
        g_er[w * 2 + 0] = r0; g_er[w * 2 + 1] = r1;
    }
}

// ---------------- GAT: segment max over incoming edges ----------------
__global__ void gatmax_kernel(const int* __restrict__ src) {
    int n = blockIdx.x * 256 + threadIdx.x;
    if (n >= NN) return;
    int beg = g_indptr[n], end = g_indptr[n + 1];
    float er0 = g_er[n * 2], er1 = g_er[n * 2 + 1];
    float m0 = -INFINITY, m1 = -INFINITY;
    for (int i = beg; i < end; i++) {
        int s = src[g_eids[i]];
        float e0 = leakyf(g_el[s * 2] + er0);
        float e1 = leakyf(g_el[s * 2 + 1] + er1);
        m0 = fmaxf(m0, e0);
        m1 = fmaxf(m1, e1);
    }
    g_mx[n * 2] = m0; g_mx[n * 2 + 1] = m1;
}

// ---------------- GAT: softmax-weighted aggregation + bias + relu (out -> g_t) ----------------
__global__ void gatagg_kernel(const int* __restrict__ src, const float* __restrict__ gbias) {
    int n = (blockIdx.x * blockDim.x + threadIdx.x) >> 5;
    if (n >= NN) return;
    int lane = threadIdx.x & 31;
    int beg = g_indptr[n], end = g_indptr[n + 1];
    float4 b0 = *(const float4*)(gbias + lane * 4);
    float4 b1 = *(const float4*)(gbias + 128 + lane * 4);
    if (beg == end) {
        float4 o0 = make_float4(fmaxf(b0.x, 0.f), fmaxf(b0.y, 0.f), fmaxf(b0.z, 0.f), fmaxf(b0.w, 0.f));
        float4 o1 = make_float4(fmaxf(b1.x, 0.f), fmaxf(b1.y, 0.f), fmaxf(b1.z, 0.f), fmaxf(b1.w, 0.f));
        *(float4*)(g_t + (size_t)n * 256 + lane * 4) = o0;
        *(float4*)(g_t + (size_t)n * 256 + 128 + lane * 4) = o1;
        return;
    }
    float er0 = g_er[n * 2], er1 = g_er[n * 2 + 1];
    float m0 = g_mx[n * 2], m1 = g_mx[n * 2 + 1];
    float den0 = 0.f, den1 = 0.f;
    float4 acc0 = make_float4(0.f, 0.f, 0.f, 0.f);
    float4 acc1 = make_float4(0.f, 0.f, 0.f, 0.f);
    for (int i = beg; i < end; i++) {
        int s = src[g_eids[i]];
        float w0 = expf(leakyf(g_el[s * 2] + er0) - m0);
        float w1 = expf(leakyf(g_el[s * 2 + 1] + er1) - m1);
        den0 += w0; den1 += w1;
        float4 z0 = *(const float4*)(g_zft + (size_t)s * 256 + lane * 4);
        float4 z1 = *(const float4*)(g_zft + (size_t)s * 256 + 128 + lane * 4);
        acc0.x += w0 * z0.x; acc0.y += w0 * z0.y; acc0.z += w0 * z0.z; acc0.w += w0 * z0.w;
        acc1.x += w1 * z1.x; acc1.y += w1 * z1.y; acc1.z += w1 * z1.z; acc1.w += w1 * z1.w;
    }
    float i0 = 1.0f / den0, i1 = 1.0f / den1;
    float4 o0, o1;
    o0.x = fmaxf(acc0.x * i0 + b0.x, 0.f); o0.y = fmaxf(acc0.y * i0 + b0.y, 0.f);
    o0.z = fmaxf(acc0.z * i0 + b0.z, 0.f); o0.w = fmaxf(acc0.w * i0 + b0.w, 0.f);
    o1.x = fmaxf(acc1.x * i1 + b1.x, 0.f); o1.y = fmaxf(acc1.y * i1 + b1.y, 0.f);
    o1.z = fmaxf(acc1.z * i1 + b1.z, 0.f); o1.w = fmaxf(acc1.w * i1 + b1.w, 0.f);
    *(float4*)(g_t + (size_t)n * 256 + lane * 4) = o0;
    *(float4*)(g_t + (size_t)n * 256 + 128 + lane * 4) = o1;
}

// ---------------- per-graph mean (two-stage, deterministic) ----------------
__global__ void meanpart_kernel() {
    int g = blockIdx.x, s = blockIdx.y, d = threadIdx.x;
    int beg = g_goff[g], end = g_goff[g + 1];
    int cnt = end - beg;
    int chunk = (cnt + 15) / 16;
    int lo = beg + s * chunk;
    int hi = min(lo + chunk, end);
    float acc = 0.f;
    for (int r = lo; r < hi; r++) acc += g_t[(size_t)r * 256 + d];
    g_part[(g * 16 + s) * 256 + d] = acc;
}

__global__ void meanred_kernel() {
    int idx = blockIdx.x * 256 + threadIdx.x;
    if (idx >= 64 * 256) return;
    int g = idx >> 8;
    float acc = 0.f;
    for (int s = 0; s < 16; s++) acc += g_part[(g * 16 + s) * 256 + (idx & 255)];
    float cnt = (float)(g_goff[g + 1] - g_goff[g]);
    g_hg[idx] = acc / fmaxf(cnt, 1.0f);
}

// ---------------- classifier ----------------
__global__ void classify_kernel(const float* __restrict__ Wc, const float* __restrict__ bc, int inst) {
    int idx = blockIdx.x * 256 + threadIdx.x;
    if (idx >= 64 * 2 * 32) return;
    int g = idx >> 6;
    int hh = (idx >> 5) & 1;
    int c = idx & 31;
    float s = bc[c];
    const float* hg = g_hg + g * 256 + hh * 128;
    const float* wr = Wc + c * 128;
    for (int d = 0; d < 128; d++) s += hg[d] * wr[d];
    g_logits[inst * 4096 + idx] = s;
}

// ---------------- final pairwise distance + head softmax ----------------
__global__ void combine_kernel(float* __restrict__ out) {
    int b = threadIdx.x;
    if (b >= 64) return;
    float dist[2];
    for (int hh = 0; hh < 2; hh++) {
        int base = b * 64 + hh * 32;
        float ss = 0.f;
        for (int c = 0; c < 32; c++) {
            float diff = g_logits[base + c] - g_logits[4096 + base + c] + 1e-6f;
            ss += diff * diff;
        }
        dist[hh] = sqrtf(ss);
    }
    float mx = fmaxf(dist[0], dist[1]);
    float e0 = expf(dist[0] - mx), e1 = expf(dist[1] - mx);
    float inv = 1.0f / (e0 + e1);
    out[b * 2 + 0] = e0 * inv;
    out[b * 2 + 1] = e1 * inv;
}

// ---------------- host ----------------
extern "C" void kernel_launch(void* const* d_in, const int* in_sizes, int n_in,
                              void* d_out, int out_size) {
    const float* in_feat[2] = {(const float*)d_in[0], (const float*)d_in[1]};
    const int* src[2]   = {(const int*)d_in[2], (const int*)d_in[6]};
    const int* dst[2]   = {(const int*)d_in[3], (const int*)d_in[7]};
    const int* etype[2] = {(const int*)d_in[4], (const int*)d_in[8]};
    const int* gid[2]   = {(const int*)d_in[5], (const int*)d_in[9]};
    const float* W_et   = (const float*)d_in[10];
    const float* b_et   = (const float*)d_in[11];
    const float* W_ih   = (const float*)d_in[12];
    const float* W_hh   = (const float*)d_in[13];
    const float* b_ih   = (const float*)d_in[14];
    const float* b_hh   = (const float*)d_in[15];
    const float* W_fc   = (const float*)d_in[16];
    const float* attn_l = (const float*)d_in[17];
    const float* attn_r = (const float*)d_in[18];
    const float* gbias  = (const float*)d_in[19];
    const float* W_cls  = (const float*)d_in[20];
    const float* b_cls  = (const float*)d_in[21];

    float *p_t, *p_a, *p_gi, *p_h, *p_zft, *p_WihB, *p_WhhB, *p_WfcB, *p_zero;
    int *p_cursor;
    cudaGetSymbolAddress((void**)&p_t, g_t);
    cudaGetSymbolAddress((void**)&p_a, g_a);
    cudaGetSymbolAddress((void**)&p_gi, g_gi);
    cudaGetSymbolAddress((void**)&p_h, g_h);
    cudaGetSymbolAddress((void**)&p_zft, g_zft);
    cudaGetSymbolAddress((void**)&p_WihB, g_WihB);
    cudaGetSymbolAddress((void**)&p_WhhB, g_WhhB);
    cudaGetSymbolAddress((void**)&p_WfcB, g_WfcB);
    cudaGetSymbolAddress((void**)&p_zero, g_zerobias);
    cudaGetSymbolAddress((void**)&p_cursor, g_cursor);

    // weight prepack
    prep_wet<<<(128 * 512 + 255) / 256, 256>>>(W_et);
    prep_tr<<<(128 * 384 + 255) / 256, 256>>>(W_ih, p_WihB, 384);
    prep_tr<<<(128 * 384 + 255) / 256, 256>>>(W_hh, p_WhhB, 384);
    prep_tr<<<(128 * 256 + 255) / 256, 256>>>(W_fc, p_WfcB, 256);

    const int EB = (EE + 255) / 256;
    const int WB = (NN * 32) / 256;  // warp-per-node grids (NN*32 threads)

    for (int inst = 0; inst < 2; inst++) {
        cudaMemcpyAsync(p_h, in_feat[inst], (size_t)NN * 128 * sizeof(float),
                        cudaMemcpyDeviceToDevice, 0);
        cudaMemsetAsync(p_cursor, 0, (NN + 1) * sizeof(int), 0);
        hist_kernel<<<EB, 256>>>(dst[inst]);
        scan_kernel<<<1, 1024>>>();
        scatter_kernel<<<EB, 256>>>(dst[inst]);
        goff_kernel<<<1, 65>>>(gid[inst]);

        for (int step = 0; step < NSTEPS; step++) {
            gemm128<<<dim3(4, 391), 256>>>(p_h, g_WcatB, b_et, p_t, 512);
            aggregate_kernel<<<WB, 256>>>(src[inst], etype[inst]);
            gemm128<<<dim3(3, 391), 256>>>(p_a, p_WihB, b_ih, p_gi, 384);
            // gh written into g_t (aliased; t already consumed by aggregate)
            gemm128<<<dim3(3, 391), 256>>>(p_h, p_WhhB, b_hh, p_t, 384);
            gru_kernel<<<(NN * 128) / 256, 256>>>();
        }

        normsig_kernel<<<WB, 256>>>();
        gemm128<<<dim3(2, 391), 256>>>(p_h, p_WfcB, p_zero, p_zft, 256);
        elr_kernel<<<WB, 256>>>(attn_l, attn_r);
        gatmax_kernel<<<(NN + 255) / 256, 256>>>(src[inst]);
        gatagg_kernel<<<WB, 256>>>(src[inst], gbias);
        meanpart_kernel<<<dim3(64, 16), 256>>>();
        meanred_kernel<<<64, 256>>>();
        classify_kernel<<<16, 256>>>(W_cls, b_cls, inst);
    }
    combine_kernel<<<1, 64>>>((float*)d_out);
}

// round 3
// speedup vs baseline: 1.9962x; 1.9962x over previous
#include <cuda_runtime.h>
#include <cuda_bf16.h>
#include <math.h>

#define NN 50000
#define EE 600000
#define NSTEPS 5

// ---------------- scratch (device globals: allocation-free) ----------------
__device__ float g_t[(size_t)NN * 512];     // per-etype transformed feats; reused as gh [NN,384] and GAT out [NN,256]
__device__ float g_a[(size_t)NN * 128];     // aggregated messages
__device__ float g_gi[(size_t)NN * 384];
__device__ float g_h[(size_t)NN * 128];     // current hidden state
__device__ float g_zft[(size_t)NN * 256];   // GAT projection
__device__ float g_el[NN * 2];
__device__ float g_er[NN * 2];
__device__ float g_mx[NN * 2];
__device__ int   g_indptr[NN + 1];
__device__ int   g_cursor[NN + 1];
__device__ int   g_eids[EE];
__device__ int   g_goff[65];
__device__ float g_part[64 * 16 * 256];
__device__ float g_hg[64 * 256];
__device__ float g_logits[2 * 64 * 2 * 32];
__device__ float g_zerobias[512];           // stays zero (bss)

// bf16 split operand buffers
__device__ __nv_bfloat16 g_cvAh[(size_t)NN * 128];
__device__ __nv_bfloat16 g_cvAl[(size_t)NN * 128];
__device__ __nv_bfloat16 g_cvBh[(size_t)NN * 128];
__device__ __nv_bfloat16 g_cvBl[(size_t)NN * 128];
__device__ __nv_bfloat16 g_Weth[512 * 128];
__device__ __nv_bfloat16 g_Wetl[512 * 128];
__device__ __nv_bfloat16 g_Wihh[384 * 128];
__device__ __nv_bfloat16 g_Wihl[384 * 128];
__device__ __nv_bfloat16 g_Whhh[384 * 128];
__device__ __nv_bfloat16 g_Whhl[384 * 128];
__device__ __nv_bfloat16 g_Wfch[256 * 128];
__device__ __nv_bfloat16 g_Wfcl[256 * 128];

__device__ __forceinline__ float sigf(float x) { return 1.0f / (1.0f + expf(-x)); }
__device__ __forceinline__ float leakyf(float x) { return x > 0.0f ? x : 0.2f * x; }

// ---------------- fp32 -> (bf16 hi, bf16 lo) split ----------------
__global__ void conv_split(const float* __restrict__ src,
                           __nv_bfloat16* __restrict__ hi,
                           __nv_bfloat16* __restrict__ lo, int n) {
    int i = blockIdx.x * 256 + threadIdx.x;
    if (i >= n) return;
    float x = src[i];
    __nv_bfloat16 h = __float2bfloat16(x);
    hi[i] = h;
    lo[i] = __float2bfloat16(x - __bfloat162float(h));
}

// ---------------- CSR build ----------------
__global__ void hist_kernel(const int* __restrict__ dst) {
    int i = blockIdx.x * 256 + threadIdx.x;
    if (i < EE) atomicAdd(&g_cursor[dst[i]], 1);
}

__global__ void scan_kernel() {
    __shared__ int sm[1024];
    int tid = threadIdx.x;
    const int n = NN;
    int chunk = (n + 1023) / 1024;
    int start = tid * chunk;
    int end = min(start + chunk, n);
    int s = 0;
    for (int i = start; i < end; i++) s += g_cursor[i];
    sm[tid] = s;
    __syncthreads();
    for (int off = 1; off < 1024; off <<= 1) {
        int v = (tid >= off) ? sm[tid - off] : 0;
        __syncthreads();
        sm[tid] += v;
        __syncthreads();
    }
    int run = (tid == 0) ? 0 : sm[tid - 1];
    for (int i = start; i < end; i++) {
        int c = g_cursor[i];
        g_indptr[i] = run;
        g_cursor[i] = run;
        run += c;
    }
    if (tid == 1023) g_indptr[n] = run;
}

__global__ void scatter_kernel(const int* __restrict__ dst) {
    int i = blockIdx.x * 256 + threadIdx.x;
    if (i >= EE) return;
    int pos = atomicAdd(&g_cursor[dst[i]], 1);
    g_eids[pos] = i;
}

__global__ void goff_kernel(const int* __restrict__ gid) {
    int g = threadIdx.x;
    if (g > 64) return;
    int lo = 0, hi = NN;
    while (lo < hi) {
        int mid = (lo + hi) >> 1;
        if (gid[mid] < g) lo = mid + 1; else hi = mid;
    }
    g_goff[g] = lo;
}

// ---------------- tensor-core GEMM: C[NN,Ntot] = A[NN,128] x B[Ntot,128]^T + bias ----
// A, B given as bf16 (hi, lo) splits; 3-product accumulation in fp32.
__device__ __forceinline__ void ldsm_x4(unsigned& r0, unsigned& r1, unsigned& r2, unsigned& r3,
                                        unsigned addr) {
    asm volatile("ldmatrix.sync.aligned.m8n8.x4.shared.b16 {%0,%1,%2,%3}, [%4];\n"
                 : "=r"(r0), "=r"(r1), "=r"(r2), "=r"(r3) : "r"(addr));
}

__device__ __forceinline__ void mma_bf16(float* c, const unsigned* a, const unsigned* b) {
    asm volatile(
        "mma.sync.aligned.m16n8k16.row.col.f32.bf16.bf16.f32 "
        "{%0,%1,%2,%3},{%4,%5,%6,%7},{%8,%9},{%0,%1,%2,%3};\n"
        : "+f"(c[0]), "+f"(c[1]), "+f"(c[2]), "+f"(c[3])
        : "r"(a[0]), "r"(a[1]), "r"(a[2]), "r"(a[3]), "r"(b[0]), "r"(b[1]));
}

#define LDA 136   // padded k-stride (elements) for smem tiles
#define SMEM_GEMM_BYTES ((128 * LDA * 2 + 64 * LDA * 2) * 2)

__global__ void __launch_bounds__(256, 2) gemm_mma(
    const __nv_bfloat16* __restrict__ Ahi, const __nv_bfloat16* __restrict__ Alo,
    const __nv_bfloat16* __restrict__ Bhi, const __nv_bfloat16* __restrict__ Blo,
    const float* __restrict__ bias, float* __restrict__ C, int Ntot)
{
    extern __shared__ __nv_bfloat16 sm[];
    __nv_bfloat16* sAh = sm;
    __nv_bfloat16* sAl = sAh + 128 * LDA;
    __nv_bfloat16* sBh = sAl + 128 * LDA;
    __nv_bfloat16* sBl = sBh + 64 * LDA;

    const int tid = threadIdx.x;
    const int brow = blockIdx.y * 128;
    const int bcol = blockIdx.x * 64;

    // stage A (128 x 128) hi+lo
    for (int i = tid; i < 128 * 16; i += 256) {
        int r = i >> 4, c = (i & 15) << 3;
        int gr = brow + r;
        uint4 vh = make_uint4(0u, 0u, 0u, 0u), vl = vh;
        if (gr < NN) {
            vh = *(const uint4*)(Ahi + (size_t)gr * 128 + c);
            vl = *(const uint4*)(Alo + (size_t)gr * 128 + c);
        }
        *(uint4*)(sAh + r * LDA + c) = vh;
        *(uint4*)(sAl + r * LDA + c) = vl;
    }
    // stage B (64 x 128) hi+lo (always in range; Ntot multiple of 64)
    for (int i = tid; i < 64 * 16; i += 256) {
        int r = i >> 4, c = (i & 15) << 3;
        *(uint4*)(sBh + r * LDA + c) = *(const uint4*)(Bhi + (size_t)(bcol + r) * 128 + c);
        *(uint4*)(sBl + r * LDA + c) = *(const uint4*)(Blo + (size_t)(bcol + r) * 128 + c);
    }
    __syncthreads();

    const int wid = tid >> 5, lane = tid & 31;
    const int wr = (wid & 3) * 32;
    const int wc = (wid >> 2) * 32;

    float acc[2][4][4];
#pragma unroll
    for (int mi = 0; mi < 2; mi++)
#pragma unroll
        for (int nj = 0; nj < 4; nj++)
#pragma unroll
            for (int q = 0; q < 4; q++) acc[mi][nj][q] = 0.0f;

    const int la_r = lane & 15;
    const int la_c = (lane & 16) ? 8 : 0;
    const int lb_r = (lane & 7) + ((lane & 16) ? 8 : 0);
    const int lb_c = (lane & 8) ? 8 : 0;

    const unsigned baseAh = (unsigned)__cvta_generic_to_shared(sAh);
    const unsigned baseAl = (unsigned)__cvta_generic_to_shared(sAl);
    const unsigned baseBh = (unsigned)__cvta_generic_to_shared(sBh);
    const unsigned baseBl = (unsigned)__cvta_generic_to_shared(sBl);

#pragma unroll
    for (int kc = 0; kc < 8; kc++) {
        const int k0 = kc * 16;
        unsigned ah[2][4], al[2][4], bh[4][2], bl[4][2];
#pragma unroll
        for (int mi = 0; mi < 2; mi++) {
            unsigned off = (unsigned)(((wr + mi * 16 + la_r) * LDA + k0 + la_c) * 2);
            ldsm_x4(ah[mi][0], ah[mi][1], ah[mi][2], ah[mi][3], baseAh + off);
            ldsm_x4(al[mi][0], al[mi][1], al[mi][2], al[mi][3], baseAl + off);
        }
#pragma unroll
        for (int np = 0; np < 2; np++) {
            unsigned off = (unsigned)(((wc + np * 16 + lb_r) * LDA + k0 + lb_c) * 2);
            unsigned r0, r1, r2, r3;
            ldsm_x4(r0, r1, r2, r3, baseBh + off);
            bh[np * 2][0] = r0; bh[np * 2][1] = r1;
            bh[np * 2 + 1][0] = r2; bh[np * 2 + 1][1] = r3;
            ldsm_x4(r0, r1, r2, r3, baseBl + off);
            bl[np * 2][0] = r0; bl[np * 2][1] = r1;
            bl[np * 2 + 1][0] = r2; bl[np * 2 + 1][1] = r3;
        }
#pragma unroll
        for (int mi = 0; mi < 2; mi++)
#pragma unroll
            for (int nj = 0; nj < 4; nj++) {
                mma_bf16(acc[mi][nj], ah[mi], bh[nj]);   // hi*hi
                mma_bf16(acc[mi][nj], al[mi], bh[nj]);   // lo*hi
                mma_bf16(acc[mi][nj], ah[mi], bl[nj]);   // hi*lo
            }
    }

    // epilogue: add bias, store fp32
    const int g = lane >> 2, t4 = lane & 3;
#pragma unroll
    for (int mi = 0; mi < 2; mi++) {
#pragma unroll
        for (int nj = 0; nj < 4; nj++) {
            int col = bcol + wc + nj * 8 + t4 * 2;
            float bx = bias[col], by = bias[col + 1];
            int r0 = brow + wr + mi * 16 + g;
            if (r0 < NN) {
                float2 o = make_float2(acc[mi][nj][0] + bx, acc[mi][nj][1] + by);
                *(float2*)(C + (size_t)r0 * Ntot + col) = o;
            }
            int r1 = r0 + 8;
            if (r1 < NN) {
                float2 o = make_float2(acc[mi][nj][2] + bx, acc[mi][nj][3] + by);
                *(float2*)(C + (size_t)r1 * Ntot + col) = o;
            }
        }
    }
}

// ---------------- message aggregation: a[d] = sum over in-edges of t[etype,src] ----------------
__global__ void aggregate_kernel(const int* __restrict__ src, const int* __restrict__ et) {
    int w = (blockIdx.x * blockDim.x + threadIdx.x) >> 5;
    if (w >= NN) return;
    int lane = threadIdx.x & 31;
    int beg = g_indptr[w], end = g_indptr[w + 1];
    float4 acc = make_float4(0.f, 0.f, 0.f, 0.f);
    for (int i = beg; i < end; i++) {
        int e = g_eids[i];
        const float4 v = *(const float4*)(g_t + (size_t)src[e] * 512 + et[e] * 128 + lane * 4);
        acc.x += v.x; acc.y += v.y; acc.z += v.z; acc.w += v.w;
    }
    *(float4*)(g_a + (size_t)w * 128 + lane * 4) = acc;
}

// ---------------- GRU elementwise (gh lives in g_t, reused) ----------------
__global__ void gru_kernel() {
    int idx = blockIdx.x * 256 + threadIdx.x;
    if (idx >= NN * 128) return;
    int n = idx >> 7, d = idx & 127;
    const float* gi = g_gi + (size_t)n * 384;
    const float* gh = g_t + (size_t)n * 384;   // aliased into g_t
    float r = sigf(gi[d] + gh[d]);
    float z = sigf(gi[128 + d] + gh[128 + d]);
    float nn_ = tanhf(gi[256 + d] + r * gh[256 + d]);
    g_h[idx] = (1.0f - z) * nn_ + z * g_h[idx];
}

// ---------------- L2 normalize + sigmoid ----------------
__global__ void normsig_kernel() {
    int w = (blockIdx.x * blockDim.x + threadIdx.x) >> 5;
    if (w >= NN) return;
    int lane = threadIdx.x & 31;
    float4 v = *(float4*)(g_h + (size_t)w * 128 + lane * 4);
    float ss = v.x * v.x + v.y * v.y + v.z * v.z + v.w * v.w;
    for (int o = 16; o; o >>= 1) ss += __shfl_xor_sync(0xffffffff, ss, o);
    float inv = 1.0f / fmaxf(sqrtf(ss), 1e-12f);
    v.x = sigf(v.x * inv);
    v.y = sigf(v.y * inv);
    v.z = sigf(v.z * inv);
    v.w = sigf(v.w * inv);
    *(float4*)(g_h + (size_t)w * 128 + lane * 4) = v;
}

// ---------------- GAT: el/er per node ----------------
__global__ void elr_kernel(const float* __restrict__ al, const float* __restrict__ ar) {
    int w = (blockIdx.x * blockDim.x + threadIdx.x) >> 5;
    if (w >= NN) return;
    int lane = threadIdx.x & 31;
    float4 z0 = *(float4*)(g_zft + (size_t)w * 256 + lane * 4);
    float4 z1 = *(float4*)(g_zft + (size_t)w * 256 + 128 + lane * 4);
    float4 l0v = *(const float4*)(al + lane * 4);
    float4 l1v = *(const float4*)(al + 128 + lane * 4);
    float4 r0v = *(const float4*)(ar + lane * 4);
    float4 r1v = *(const float4*)(ar + 128 + lane * 4);
    float l0 = z0.x * l0v.x + z0.y * l0v.y + z0.z * l0v.z + z0.w * l0v.w;
    float l1 = z1.x * l1v.x + z1.y * l1v.y + z1.z * l1v.z + z1.w * l1v.w;
    float r0 = z0.x * r0v.x + z0.y * r0v.y + z0.z * r0v.z + z0.w * r0v.w;
    float r1 = z1.x * r1v.x + z1.y * r1v.y + z1.z * r1v.z + z1.w * r1v.w;
    for (int o = 16; o; o >>= 1) {
        l0 += __shfl_xor_sync(0xffffffff, l0, o);
        l1 += __shfl_xor_sync(0xffffffff, l1, o);
        r0 += __shfl_xor_sync(0xffffffff, r0, o);
        r1 += __shfl_xor_sync(0xffffffff, r1, o);
    }
    if (lane == 0) {
        g_el[w * 2 + 0] = l0; g_el[w * 2 + 1] = l1;
        g_er[w * 2 + 0] = r0; g_er[w * 2 + 1] = r1;
    }
}

// ---------------- GAT: segment max over incoming edges ----------------
__global__ void gatmax_kernel(const int* __restrict__ src) {
    int n = blockIdx.x * 256 + threadIdx.x;
    if (n >= NN) return;
    int beg = g_indptr[n], end = g_indptr[n + 1];
    float er0 = g_er[n * 2], er1 = g_er[n * 2 + 1];
    float m0 = -INFINITY, m1 = -INFINITY;
    for (int i = beg; i < end; i++) {
        int s = src[g_eids[i]];
        float e0 = leakyf(g_el[s * 2] + er0);
        float e1 = leakyf(g_el[s * 2 + 1] + er1);
        m0 = fmaxf(m0, e0);
        m1 = fmaxf(m1, e1);
    }
    g_mx[n * 2] = m0; g_mx[n * 2 + 1] = m1;
}

// ---------------- GAT: softmax-weighted aggregation + bias + relu (out -> g_t) ----------------
__global__ void gatagg_kernel(const int* __restrict__ src, const float* __restrict__ gbias) {
    int n = (blockIdx.x * blockDim.x + threadIdx.x) >> 5;
    if (n >= NN) return;
    int lane = threadIdx.x & 31;
    int beg = g_indptr[n], end = g_indptr[n + 1];
    float4 b0 = *(const float4*)(gbias + lane * 4);
    float4 b1 = *(const float4*)(gbias + 128 + lane * 4);
    if (beg == end) {
        float4 o0 = make_float4(fmaxf(b0.x, 0.f), fmaxf(b0.y, 0.f), fmaxf(b0.z, 0.f), fmaxf(b0.w, 0.f));
        float4 o1 = make_float4(fmaxf(b1.x, 0.f), fmaxf(b1.y, 0.f), fmaxf(b1.z, 0.f), fmaxf(b1.w, 0.f));
        *(float4*)(g_t + (size_t)n * 256 + lane * 4) = o0;
        *(float4*)(g_t + (size_t)n * 256 + 128 + lane * 4) = o1;
        return;
    }
    float er0 = g_er[n * 2], er1 = g_er[n * 2 + 1];
    float m0 = g_mx[n * 2], m1 = g_mx[n * 2 + 1];
    float den0 = 0.f, den1 = 0.f;
    float4 acc0 = make_float4(0.f, 0.f, 0.f, 0.f);
    float4 acc1 = make_float4(0.f, 0.f, 0.f, 0.f);
    for (int i = beg; i < end; i++) {
        int s = src[g_eids[i]];
        float w0 = expf(leakyf(g_el[s * 2] + er0) - m0);
        float w1 = expf(leakyf(g_el[s * 2 + 1] + er1) - m1);
        den0 += w0; den1 += w1;
        float4 z0 = *(const float4*)(g_zft + (size_t)s * 256 + lane * 4);
        float4 z1 = *(const float4*)(g_zft + (size_t)s * 256 + 128 + lane * 4);
        acc0.x += w0 * z0.x; acc0.y += w0 * z0.y; acc0.z += w0 * z0.z; acc0.w += w0 * z0.w;
        acc1.x += w1 * z1.x; acc1.y += w1 * z1.y; acc1.z += w1 * z1.z; acc1.w += w1 * z1.w;
    }
    float i0 = 1.0f / den0, i1 = 1.0f / den1;
    float4 o0, o1;
    o0.x = fmaxf(acc0.x * i0 + b0.x, 0.f); o0.y = fmaxf(acc0.y * i0 + b0.y, 0.f);
    o0.z = fmaxf(acc0.z * i0 + b0.z, 0.f); o0.w = fmaxf(acc0.w * i0 + b0.w, 0.f);
    o1.x = fmaxf(acc1.x * i1 + b1.x, 0.f); o1.y = fmaxf(acc1.y * i1 + b1.y, 0.f);
    o1.z = fmaxf(acc1.z * i1 + b1.z, 0.f); o1.w = fmaxf(acc1.w * i1 + b1.w, 0.f);
    *(float4*)(g_t + (size_t)n * 256 + lane * 4) = o0;
    *(float4*)(g_t + (size_t)n * 256 + 128 + lane * 4) = o1;
}

// ---------------- per-graph mean (two-stage, deterministic) ----------------
__global__ void meanpart_kernel() {
    int g = blockIdx.x, s = blockIdx.y, d = threadIdx.x;
    int beg = g_goff[g], end = g_goff[g + 1];
    int cnt = end - beg;
    int chunk = (cnt + 15) / 16;
    int lo = beg + s * chunk;
    int hi = min(lo + chunk, end);
    float acc = 0.f;
    for (int r = lo; r < hi; r++) acc += g_t[(size_t)r * 256 + d];
    g_part[(g * 16 + s) * 256 + d] = acc;
}

__global__ void meanred_kernel() {
    int idx = blockIdx.x * 256 + threadIdx.x;
    if (idx >= 64 * 256) return;
    int g = idx >> 8;
    float acc = 0.f;
    for (int s = 0; s < 16; s++) acc += g_part[(g * 16 + s) * 256 + (idx & 255)];
    float cnt = (float)(g_goff[g + 1] - g_goff[g]);
    g_hg[idx] = acc / fmaxf(cnt, 1.0f);
}

// ---------------- classifier ----------------
__global__ void classify_kernel(const float* __restrict__ Wc, const float* __restrict__ bc, int inst) {
    int idx = blockIdx.x * 256 + threadIdx.x;
    if (idx >= 64 * 2 * 32) return;
    int g = idx >> 6;
    int hh = (idx >> 5) & 1;
    int c = idx & 31;
    float s = bc[c];
    const float* hg = g_hg + g * 256 + hh * 128;
    const float* wr = Wc + c * 128;
    for (int d = 0; d < 128; d++) s += hg[d] * wr[d];
    g_logits[inst * 4096 + idx] = s;
}

// ---------------- final pairwise distance + head softmax ----------------
__global__ void combine_kernel(float* __restrict__ out) {
    int b = threadIdx.x;
    if (b >= 64) return;
    float dist[2];
    for (int hh = 0; hh < 2; hh++) {
        int base = b * 64 + hh * 32;
        float ss = 0.f;
        for (int c = 0; c < 32; c++) {
            float diff = g_logits[base + c] - g_logits[4096 + base + c] + 1e-6f;
            ss += diff * diff;
        }
        dist[hh] = sqrtf(ss);
    }
    float mx = fmaxf(dist[0], dist[1]);
    float e0 = expf(dist[0] - mx), e1 = expf(dist[1] - mx);
    float inv = 1.0f / (e0 + e1);
    out[b * 2 + 0] = e0 * inv;
    out[b * 2 + 1] = e1 * inv;
}

// ---------------- host ----------------
extern "C" void kernel_launch(void* const* d_in, const int* in_sizes, int n_in,
                              void* d_out, int out_size) {
    const float* in_feat[2] = {(const float*)d_in[0], (const float*)d_in[1]};
    const int* src[2]   = {(const int*)d_in[2], (const int*)d_in[6]};
    const int* dst[2]   = {(const int*)d_in[3], (const int*)d_in[7]};
    const int* etype[2] = {(const int*)d_in[4], (const int*)d_in[8]};
    const int* gid[2]   = {(const int*)d_in[5], (const int*)d_in[9]};
    const float* W_et   = (const float*)d_in[10];
    const float* b_et   = (const float*)d_in[11];
    const float* W_ih   = (const float*)d_in[12];
    const float* W_hh   = (const float*)d_in[13];
    const float* b_ih   = (const float*)d_in[14];
    const float* b_hh   = (const float*)d_in[15];
    const float* W_fc   = (const float*)d_in[16];
    const float* attn_l = (const float*)d_in[17];
    const float* attn_r = (const float*)d_in[18];
    const float* gbias  = (const float*)d_in[19];
    const float* W_cls  = (const float*)d_in[20];
    const float* b_cls  = (const float*)d_in[21];

    float *p_t, *p_a, *p_gi, *p_h, *p_zft, *p_zero;
    int *p_cursor;
    __nv_bfloat16 *p_cvAh, *p_cvAl, *p_cvBh, *p_cvBl;
    __nv_bfloat16 *p_Weth, *p_Wetl, *p_Wihh, *p_Wihl, *p_Whhh, *p_Whhl, *p_Wfch, *p_Wfcl;
    cudaGetSymbolAddress((void**)&p_t, g_t);
    cudaGetSymbolAddress((void**)&p_a, g_a);
    cudaGetSymbolAddress((void**)&p_gi, g_gi);
    cudaGetSymbolAddress((void**)&p_h, g_h);
    cudaGetSymbolAddress((void**)&p_zft, g_zft);
    cudaGetSymbolAddress((void**)&p_zero, g_zerobias);
    cudaGetSymbolAddress((void**)&p_cursor, g_cursor);
    cudaGetSymbolAddress((void**)&p_cvAh, g_cvAh);
    cudaGetSymbolAddress((void**)&p_cvAl, g_cvAl);
    cudaGetSymbolAddress((void**)&p_cvBh, g_cvBh);
    cudaGetSymbolAddress((void**)&p_cvBl, g_cvBl);
    cudaGetSymbolAddress((void**)&p_Weth, g_Weth);
    cudaGetSymbolAddress((void**)&p_Wetl, g_Wetl);
    cudaGetSymbolAddress((void**)&p_Wihh, g_Wihh);
    cudaGetSymbolAddress((void**)&p_Wihl, g_Wihl);
    cudaGetSymbolAddress((void**)&p_Whhh, g_Whhh);
    cudaGetSymbolAddress((void**)&p_Whhl, g_Whhl);
    cudaGetSymbolAddress((void**)&p_Wfch, g_Wfch);
    cudaGetSymbolAddress((void**)&p_Wfcl, g_Wfcl);

    cudaFuncSetAttribute(gemm_mma, cudaFuncAttributeMaxDynamicSharedMemorySize, SMEM_GEMM_BYTES);

    // weight conversions (once per launch)
    conv_split<<<(512 * 128 + 255) / 256, 256>>>(W_et, p_Weth, p_Wetl, 512 * 128);
    conv_split<<<(384 * 128 + 255) / 256, 256>>>(W_ih, p_Wihh, p_Wihl, 384 * 128);
    conv_split<<<(384 * 128 + 255) / 256, 256>>>(W_hh, p_Whhh, p_Whhl, 384 * 128);
    conv_split<<<(256 * 128 + 255) / 256, 256>>>(W_fc, p_Wfch, p_Wfcl, 256 * 128);

    const int EB = (EE + 255) / 256;
    const int WB = (NN * 32) / 256;
    const int CB = (NN * 128 + 255) / 256;  // conversion grid for [NN,128]

    for (int inst = 0; inst < 2; inst++) {
        cudaMemcpyAsync(p_h, in_feat[inst], (size_t)NN * 128 * sizeof(float),
                        cudaMemcpyDeviceToDevice, 0);
        cudaMemsetAsync(p_cursor, 0, (NN + 1) * sizeof(int), 0);
        hist_kernel<<<EB, 256>>>(dst[inst]);
        scan_kernel<<<1, 1024>>>();
        scatter_kernel<<<EB, 256>>>(dst[inst]);
        goff_kernel<<<1, 65>>>(gid[inst]);

        for (int step = 0; step < NSTEPS; step++) {
            conv_split<<<CB, 256>>>(p_h, p_cvAh, p_cvAl, NN * 128);
            gemm_mma<<<dim3(8, 391), 256, SMEM_GEMM_BYTES>>>(
                p_cvAh, p_cvAl, p_Weth, p_Wetl, b_et, p_t, 512);
            aggregate_kernel<<<WB, 256>>>(src[inst], etype[inst]);
            conv_split<<<CB, 256>>>(p_a, p_cvBh, p_cvBl, NN * 128);
            // gh written into g_t (aliased; t already consumed by aggregate)
            gemm_mma<<<dim3(6, 391), 256, SMEM_GEMM_BYTES>>>(
                p_cvAh, p_cvAl, p_Whhh, p_Whhl, b_hh, p_t, 384);
            gemm_mma<<<dim3(6, 391), 256, SMEM_GEMM_BYTES>>>(
                p_cvBh, p_cvBl, p_Wihh, p_Wihl, b_ih, p_gi, 384);
            gru_kernel<<<(NN * 128) / 256, 256>>>();
        }

        normsig_kernel<<<WB, 256>>>();
        conv_split<<<CB, 256>>>(p_h, p_cvAh, p_cvAl, NN * 128);
        gemm_mma<<<dim3(4, 391), 256, SMEM_GEMM_BYTES>>>(
            p_cvAh, p_cvAl, p_Wfch, p_Wfcl, p_zero, p_zft, 256);
        elr_kernel<<<WB, 256>>>(attn_l, attn_r);
        gatmax_kernel<<<(NN + 255) / 256, 256>>>(src[inst]);
        gatagg_kernel<<<WB, 256>>>(src[inst], gbias);
        meanpart_kernel<<<dim3(64, 16), 256>>>();
        meanred_kernel<<<64, 256>>>();
        classify_kernel<<<16, 256>>>(W_cls, b_cls, inst);
    }
    combine_kernel<<<1, 64>>>((float*)d_out);
}

// round 4
// speedup vs baseline: 2.1470x; 1.0756x over previous
#include <cuda_runtime.h>
#include <cuda_bf16.h>
#include <math.h>

#define NN 50000
#define EE 600000
#define NSTEPS 5
#define NI (NN + 1)

// ---------------- scratch (device globals) ----------------
__device__ float g_tg[(size_t)2 * NN * 896];   // [t(512) | gh(384)] per step; reused as GAT out [NN,256]
__device__ float g_gi[(size_t)2 * NN * 384];
__device__ float g_h[(size_t)2 * NN * 128];
__device__ float g_zft[(size_t)2 * NN * 256];
__device__ float g_el[2 * NN * 2];
__device__ float g_er[2 * NN * 2];
__device__ float g_mx[2 * NN * 2];
__device__ int   g_indptr[2 * NI];
__device__ int   g_cursor[2 * NI];
__device__ int   g_eids[2 * EE];
__device__ int   g_goff[2 * 65];
__device__ float g_part[2 * 64 * 16 * 256];
__device__ float g_hg[2 * 64 * 256];
__device__ float g_logits[2 * 64 * 2 * 32];
__device__ float g_btg[896];
__device__ float g_zerobias[512];

// bf16 split buffers
__device__ __nv_bfloat16 g_cvhh[(size_t)2 * NN * 128];  // split of h
__device__ __nv_bfloat16 g_cvhl[(size_t)2 * NN * 128];
__device__ __nv_bfloat16 g_cvah[(size_t)2 * NN * 128];  // split of a
__device__ __nv_bfloat16 g_cval[(size_t)2 * NN * 128];
__device__ __nv_bfloat16 g_Wtgh[896 * 128];
__device__ __nv_bfloat16 g_Wtgl[896 * 128];
__device__ __nv_bfloat16 g_Wihh[384 * 128];
__device__ __nv_bfloat16 g_Wihl[384 * 128];
__device__ __nv_bfloat16 g_Wfch[256 * 128];
__device__ __nv_bfloat16 g_Wfcl[256 * 128];

__device__ __forceinline__ float sigf(float x) { return 1.0f / (1.0f + expf(-x)); }
__device__ __forceinline__ float leakyf(float x) { return x > 0.0f ? x : 0.2f * x; }

__device__ __forceinline__ void split2(float x, __nv_bfloat16* hi, __nv_bfloat16* lo) {
    __nv_bfloat16 h = __float2bfloat16(x);
    *hi = h;
    *lo = __float2bfloat16(x - __bfloat162float(h));
}

// pack 4 floats -> uint2 of bf16 (hi) and uint2 (lo)
__device__ __forceinline__ void split4_store(float4 v, __nv_bfloat16* hi, __nv_bfloat16* lo) {
    __nv_bfloat16 h0, h1, h2, h3, l0, l1, l2, l3;
    split2(v.x, &h0, &l0); split2(v.y, &h1, &l1);
    split2(v.z, &h2, &l2); split2(v.w, &h3, &l3);
    uint2 ph = make_uint2(((unsigned)__bfloat16_as_ushort(h1) << 16) | __bfloat16_as_ushort(h0),
                          ((unsigned)__bfloat16_as_ushort(h3) << 16) | __bfloat16_as_ushort(h2));
    uint2 pl = make_uint2(((unsigned)__bfloat16_as_ushort(l1) << 16) | __bfloat16_as_ushort(l0),
                          ((unsigned)__bfloat16_as_ushort(l3) << 16) | __bfloat16_as_ushort(l2));
    *(uint2*)hi = ph;
    *(uint2*)lo = pl;
}

// ---------------- weight conversion ----------------
__global__ void conv_split(const float* __restrict__ src,
                           __nv_bfloat16* __restrict__ hi,
                           __nv_bfloat16* __restrict__ lo, int n) {
    int i = blockIdx.x * 256 + threadIdx.x;
    if (i >= n) return;
    split2(src[i], hi + i, lo + i);
}

// ---------------- prep: copy both feats into h + split; fold bias concat ----------------
__global__ void prep_kernel(const float* __restrict__ f0, const float* __restrict__ f1,
                            const float* __restrict__ bet, const float* __restrict__ bhh) {
    int idx = blockIdx.x * 256 + threadIdx.x;
    if (idx < 896) g_btg[idx] = (idx < 512) ? bet[idx] : bhh[idx - 512];
    if (idx >= 2 * NN * 128) return;
    float x = (idx < NN * 128) ? f0[idx] : f1[idx - NN * 128];
    g_h[idx] = x;
    split2(x, g_cvhh + idx, g_cvhl + idx);
}

// ---------------- CSR build (both instances) ----------------
__global__ void hist_kernel(const int* __restrict__ d0, const int* __restrict__ d1) {
    int i = blockIdx.x * 256 + threadIdx.x;
    if (i >= EE) return;
    int inst = blockIdx.y;
    const int* dst = inst ? d1 : d0;
    atomicAdd(&g_cursor[inst * NI + dst[i]], 1);
}

__global__ void scan_kernel() {
    __shared__ int sm[1024];
    int inst = blockIdx.x;
    int* cur = g_cursor + inst * NI;
    int* ip = g_indptr + inst * NI;
    int tid = threadIdx.x;
    int chunk = (NN + 1023) / 1024;
    int start = tid * chunk;
    int end = min(start + chunk, NN);
    int s = 0;
    for (int i = start; i < end; i++) s += cur[i];
    sm[tid] = s;
    __syncthreads();
    for (int off = 1; off < 1024; off <<= 1) {
        int v = (tid >= off) ? sm[tid - off] : 0;
        __syncthreads();
        sm[tid] += v;
        __syncthreads();
    }
    int run = (tid == 0) ? 0 : sm[tid - 1];
    for (int i = start; i < end; i++) {
        int c = cur[i];
        ip[i] = run;
        cur[i] = run;
        run += c;
    }
    if (tid == 1023) ip[NN] = run;
}

__global__ void scatter_kernel(const int* __restrict__ d0, const int* __restrict__ d1) {
    int i = blockIdx.x * 256 + threadIdx.x;
    if (i >= EE) return;
    int inst = blockIdx.y;
    const int* dst = inst ? d1 : d0;
    int pos = atomicAdd(&g_cursor[inst * NI + dst[i]], 1);
    g_eids[inst * EE + pos] = i;
}

__global__ void goff_kernel(const int* __restrict__ g0, const int* __restrict__ g1) {
    int inst = blockIdx.x;
    const int* gid = inst ? g1 : g0;
    int g = threadIdx.x;
    if (g > 64) return;
    int lo = 0, hi = NN;
    while (lo < hi) {
        int mid = (lo + hi) >> 1;
        if (gid[mid] < g) lo = mid + 1; else hi = mid;
    }
    g_goff[inst * 65 + g] = lo;
}

// ---------------- tensor-core GEMM: C[NN,Ntot] = A[NN,128] x B[Ntot,128]^T + bias ----
__device__ __forceinline__ void ldsm_x4(unsigned& r0, unsigned& r1, unsigned& r2, unsigned& r3,
                                        unsigned addr) {
    asm volatile("ldmatrix.sync.aligned.m8n8.x4.shared.b16 {%0,%1,%2,%3}, [%4];\n"
                 : "=r"(r0), "=r"(r1), "=r"(r2), "=r"(r3) : "r"(addr));
}

__device__ __forceinline__ void mma_bf16(float* c, const unsigned* a, const unsigned* b) {
    asm volatile(
        "mma.sync.aligned.m16n8k16.row.col.f32.bf16.bf16.f32 "
        "{%0,%1,%2,%3},{%4,%5,%6,%7},{%8,%9},{%0,%1,%2,%3};\n"
        : "+f"(c[0]), "+f"(c[1]), "+f"(c[2]), "+f"(c[3])
        : "r"(a[0]), "r"(a[1]), "r"(a[2]), "r"(a[3]), "r"(b[0]), "r"(b[1]));
}

#define LDA 136
#define SMEM_GEMM_BYTES ((128 * LDA * 2 + 64 * LDA * 2) * 2)

__global__ void __launch_bounds__(256, 2) gemm_mma(
    const __nv_bfloat16* __restrict__ Ahi, const __nv_bfloat16* __restrict__ Alo,
    const __nv_bfloat16* __restrict__ Bhi, const __nv_bfloat16* __restrict__ Blo,
    const float* __restrict__ bias, float* __restrict__ C, int Ntot, size_t cStride)
{
    extern __shared__ __nv_bfloat16 sm[];
    __nv_bfloat16* sAh = sm;
    __nv_bfloat16* sAl = sAh + 128 * LDA;
    __nv_bfloat16* sBh = sAl + 128 * LDA;
    __nv_bfloat16* sBl = sBh + 64 * LDA;

    const int inst = blockIdx.z;
    Ahi += (size_t)inst * NN * 128;
    Alo += (size_t)inst * NN * 128;
    C   += (size_t)inst * cStride;

    const int tid = threadIdx.x;
    const int brow = blockIdx.y * 128;
    const int bcol = blockIdx.x * 64;

    for (int i = tid; i < 128 * 16; i += 256) {
        int r = i >> 4, c = (i & 15) << 3;
        int gr = brow + r;
        uint4 vh = make_uint4(0u, 0u, 0u, 0u), vl = vh;
        if (gr < NN) {
            vh = *(const uint4*)(Ahi + (size_t)gr * 128 + c);
            vl = *(const uint4*)(Alo + (size_t)gr * 128 + c);
        }
        *(uint4*)(sAh + r * LDA + c) = vh;
        *(uint4*)(sAl + r * LDA + c) = vl;
    }
    for (int i = tid; i < 64 * 16; i += 256) {
        int r = i >> 4, c = (i & 15) << 3;
        *(uint4*)(sBh + r * LDA + c) = *(const uint4*)(Bhi + (size_t)(bcol + r) * 128 + c);
        *(uint4*)(sBl + r * LDA + c) = *(const uint4*)(Blo + (size_t)(bcol + r) * 128 + c);
    }
    __syncthreads();

    const int wid = tid >> 5, lane = tid & 31;
    const int wr = (wid & 3) * 32;
    const int wc = (wid >> 2) * 32;

    float acc[2][4][4];
#pragma unroll
    for (int mi = 0; mi < 2; mi++)
#pragma unroll
        for (int nj = 0; nj < 4; nj++)
#pragma unroll
            for (int q = 0; q < 4; q++) acc[mi][nj][q] = 0.0f;

    const int la_r = lane & 15;
    const int la_c = (lane & 16) ? 8 : 0;
    const int lb_r = (lane & 7) + ((lane & 16) ? 8 : 0);
    const int lb_c = (lane & 8) ? 8 : 0;

    const unsigned baseAh = (unsigned)__cvta_generic_to_shared(sAh);
    const unsigned baseAl = (unsigned)__cvta_generic_to_shared(sAl);
    const unsigned baseBh = (unsigned)__cvta_generic_to_shared(sBh);
    const unsigned baseBl = (unsigned)__cvta_generic_to_shared(sBl);

#pragma unroll
    for (int kc = 0; kc < 8; kc++) {
        const int k0 = kc * 16;
        unsigned ah[2][4], al[2][4], bh[4][2], bl[4][2];
#pragma unroll
        for (int mi = 0; mi < 2; mi++) {
            unsigned off = (unsigned)(((wr + mi * 16 + la_r) * LDA + k0 + la_c) * 2);
            ldsm_x4(ah[mi][0], ah[mi][1], ah[mi][2], ah[mi][3], baseAh + off);
            ldsm_x4(al[mi][0], al[mi][1], al[mi][2], al[mi][3], baseAl + off);
        }
#pragma unroll
        for (int np = 0; np < 2; np++) {
            unsigned off = (unsigned)(((wc + np * 16 + lb_r) * LDA + k0 + lb_c) * 2);
            unsigned r0, r1, r2, r3;
            ldsm_x4(r0, r1, r2, r3, baseBh + off);
            bh[np * 2][0] = r0; bh[np * 2][1] = r1;
            bh[np * 2 + 1][0] = r2; bh[np * 2 + 1][1] = r3;
            ldsm_x4(r0, r1, r2, r3, baseBl + off);
            bl[np * 2][0] = r0; bl[np * 2][1] = r1;
            bl[np * 2 + 1][0] = r2; bl[np * 2 + 1][1] = r3;
        }
#pragma unroll
        for (int mi = 0; mi < 2; mi++)
#pragma unroll
            for (int nj = 0; nj < 4; nj++) {
                mma_bf16(acc[mi][nj], ah[mi], bh[nj]);
                mma_bf16(acc[mi][nj], al[mi], bh[nj]);
                mma_bf16(acc[mi][nj], ah[mi], bl[nj]);
            }
    }

    const int g = lane >> 2, t4 = lane & 3;
#pragma unroll
    for (int mi = 0; mi < 2; mi++) {
#pragma unroll
        for (int nj = 0; nj < 4; nj++) {
            int col = bcol + wc + nj * 8 + t4 * 2;
            float bx = bias[col], by = bias[col + 1];
            int r0 = brow + wr + mi * 16 + g;
            if (r0 < NN) {
                float2 o = make_float2(acc[mi][nj][0] + bx, acc[mi][nj][1] + by);
                *(float2*)(C + (size_t)r0 * Ntot + col) = o;
            }
            int r1 = r0 + 8;
            if (r1 < NN) {
                float2 o = make_float2(acc[mi][nj][2] + bx, acc[mi][nj][3] + by);
                *(float2*)(C + (size_t)r1 * Ntot + col) = o;
            }
        }
    }
}

// ---------------- message aggregation -> a split (bf16 hi/lo) ----------------
__global__ void aggregate_kernel(const int* __restrict__ s0, const int* __restrict__ s1,
                                 const int* __restrict__ e0, const int* __restrict__ e1) {
    int inst = blockIdx.y;
    int w = blockIdx.x * 8 + (threadIdx.x >> 5);
    if (w >= NN) return;
    const int* src = inst ? s1 : s0;
    const int* et = inst ? e1 : e0;
    const float* tbase = g_tg + (size_t)inst * NN * 896;
    const int* eids = g_eids + (size_t)inst * EE;
    int lane = threadIdx.x & 31;
    int beg = g_indptr[inst * NI + w], end = g_indptr[inst * NI + w + 1];
    float4 acc = make_float4(0.f, 0.f, 0.f, 0.f);
    for (int i = beg; i < end; i++) {
        int e = eids[i];
        const float4 v = *(const float4*)(tbase + (size_t)src[e] * 896 + et[e] * 128 + lane * 4);
        acc.x += v.x; acc.y += v.y; acc.z += v.z; acc.w += v.w;
    }
    size_t o = ((size_t)inst * NN + w) * 128 + lane * 4;
    split4_store(acc, g_cvah + o, g_cval + o);
}

// ---------------- GRU elementwise: h = (1-z)*nn + z*h; also emit h split ----------------
__global__ void gru_kernel() {
    int idx = blockIdx.x * 256 + threadIdx.x;
    if (idx >= 2 * NN * 128) return;
    int n_all = idx >> 7, d = idx & 127;
    int inst = (n_all >= NN);
    int n = n_all - inst * NN;
    const float* gi = g_gi + ((size_t)inst * NN + n) * 384;
    const float* gh = g_tg + ((size_t)inst * NN + n) * 896 + 512;
    float r = sigf(gi[d] + gh[d]);
    float z = sigf(gi[128 + d] + gh[128 + d]);
    float nn_ = tanhf(gi[256 + d] + r * gh[256 + d]);
    float h = (1.0f - z) * nn_ + z * g_h[idx];
    g_h[idx] = h;
    split2(h, g_cvhh + idx, g_cvhl + idx);
}

// ---------------- L2 normalize + sigmoid; emit h split ----------------
__global__ void normsig_kernel() {
    int w = (blockIdx.x * blockDim.x + threadIdx.x) >> 5;
    if (w >= 2 * NN) return;
    int lane = threadIdx.x & 31;
    size_t o = (size_t)w * 128 + lane * 4;
    float4 v = *(float4*)(g_h + o);
    float ss = v.x * v.x + v.y * v.y + v.z * v.z + v.w * v.w;
    for (int of = 16; of; of >>= 1) ss += __shfl_xor_sync(0xffffffff, ss, of);
    float inv = 1.0f / fmaxf(sqrtf(ss), 1e-12f);
    v.x = sigf(v.x * inv); v.y = sigf(v.y * inv);
    v.z = sigf(v.z * inv); v.w = sigf(v.w * inv);
    *(float4*)(g_h + o) = v;
    split4_store(v, g_cvhh + o, g_cvhl + o);
}

// ---------------- GAT: el/er per node ----------------
__global__ void elr_kernel(const float* __restrict__ al, const float* __restrict__ ar) {
    int w = (blockIdx.x * blockDim.x + threadIdx.x) >> 5;
    if (w >= 2 * NN) return;
    int lane = threadIdx.x & 31;
    float4 z0 = *(float4*)(g_zft + (size_t)w * 256 + lane * 4);
    float4 z1 = *(float4*)(g_zft + (size_t)w * 256 + 128 + lane * 4);
    float4 l0v = *(const float4*)(al + lane * 4);
    float4 l1v = *(const float4*)(al + 128 + lane * 4);
    float4 r0v = *(const float4*)(ar + lane * 4);
    float4 r1v = *(const float4*)(ar + 128 + lane * 4);
    float l0 = z0.x * l0v.x + z0.y * l0v.y + z0.z * l0v.z + z0.w * l0v.w;
    float l1 = z1.x * l1v.x + z1.y * l1v.y + z1.z * l1v.z + z1.w * l1v.w;
    float r0 = z0.x * r0v.x + z0.y * r0v.y + z0.z * r0v.z + z0.w * r0v.w;
    float r1 = z1.x * r1v.x + z1.y * r1v.y + z1.z * r1v.z + z1.w * r1v.w;
    for (int o = 16; o; o >>= 1) {
        l0 += __shfl_xor_sync(0xffffffff, l0, o);
        l1 += __shfl_xor_sync(0xffffffff, l1, o);
        r0 += __shfl_xor_sync(0xffffffff, r0, o);
        r1 += __shfl_xor_sync(0xffffffff, r1, o);
    }
    if (lane == 0) {
        g_el[w * 2 + 0] = l0; g_el[w * 2 + 1] = l1;
        g_er[w * 2 + 0] = r0; g_er[w * 2 + 1] = r1;
    }
}

// ---------------- GAT: segment max ----------------
__global__ void gatmax_kernel(const int* __restrict__ s0, const int* __restrict__ s1) {
    int n = blockIdx.x * 256 + threadIdx.x;
    if (n >= NN) return;
    int inst = blockIdx.y;
    const int* src = inst ? s1 : s0;
    const int* eids = g_eids + (size_t)inst * EE;
    int beg = g_indptr[inst * NI + n], end = g_indptr[inst * NI + n + 1];
    int nb = inst * NN + n;
    float er0 = g_er[nb * 2], er1 = g_er[nb * 2 + 1];
    float m0 = -INFINITY, m1 = -INFINITY;
    for (int i = beg; i < end; i++) {
        int s = inst * NN + src[eids[i]];
        float e0 = leakyf(g_el[s * 2] + er0);
        float e1 = leakyf(g_el[s * 2 + 1] + er1);
        m0 = fmaxf(m0, e0);
        m1 = fmaxf(m1, e1);
    }
    g_mx[nb * 2] = m0; g_mx[nb * 2 + 1] = m1;
}

// ---------------- GAT: softmax aggregate + bias + relu -> g_tg (stride 256) ----------------
__global__ void gatagg_kernel(const int* __restrict__ s0, const int* __restrict__ s1,
                              const float* __restrict__ gbias) {
    int inst = blockIdx.y;
    int n = blockIdx.x * 8 + (threadIdx.x >> 5);
    if (n >= NN) return;
    const int* src = inst ? s1 : s0;
    const int* eids = g_eids + (size_t)inst * EE;
    float* outb = g_tg + (size_t)inst * NN * 896;
    int lane = threadIdx.x & 31;
    int beg = g_indptr[inst * NI + n], end = g_indptr[inst * NI + n + 1];
    float4 b0 = *(const float4*)(gbias + lane * 4);
    float4 b1 = *(const float4*)(gbias + 128 + lane * 4);
    int nb = inst * NN + n;
    if (beg == end) {
        float4 o0 = make_float4(fmaxf(b0.x, 0.f), fmaxf(b0.y, 0.f), fmaxf(b0.z, 0.f), fmaxf(b0.w, 0.f));
        float4 o1 = make_float4(fmaxf(b1.x, 0.f), fmaxf(b1.y, 0.f), fmaxf(b1.z, 0.f), fmaxf(b1.w, 0.f));
        *(float4*)(outb + (size_t)n * 256 + lane * 4) = o0;
        *(float4*)(outb + (size_t)n * 256 + 128 + lane * 4) = o1;
        return;
    }
    float er0 = g_er[nb * 2], er1 = g_er[nb * 2 + 1];
    float m0 = g_mx[nb * 2], m1 = g_mx[nb * 2 + 1];
    float den0 = 0.f, den1 = 0.f;
    float4 acc0 = make_float4(0.f, 0.f, 0.f, 0.f);
    float4 acc1 = make_float4(0.f, 0.f, 0.f, 0.f);
    for (int i = beg; i < end; i++) {
        int s = inst * NN + src[eids[i]];
        float w0 = expf(leakyf(g_el[s * 2] + er0) - m0);
        float w1 = expf(leakyf(g_el[s * 2 + 1] + er1) - m1);
        den0 += w0; den1 += w1;
        float4 z0 = *(const float4*)(g_zft + (size_t)s * 256 + lane * 4);
        float4 z1 = *(const float4*)(g_zft + (size_t)s * 256 + 128 + lane * 4);
        acc0.x += w0 * z0.x; acc0.y += w0 * z0.y; acc0.z += w0 * z0.z; acc0.w += w0 * z0.w;
        acc1.x += w1 * z1.x; acc1.y += w1 * z1.y; acc1.z += w1 * z1.z; acc1.w += w1 * z1.w;
    }
    float i0 = 1.0f / den0, i1 = 1.0f / den1;
    float4 o0, o1;
    o0.x = fmaxf(acc0.x * i0 + b0.x, 0.f); o0.y = fmaxf(acc0.y * i0 + b0.y, 0.f);
    o0.z = fmaxf(acc0.z * i0 + b0.z, 0.f); o0.w = fmaxf(acc0.w * i0 + b0.w, 0.f);
    o1.x = fmaxf(acc1.x * i1 + b1.x, 0.f); o1.y = fmaxf(acc1.y * i1 + b1.y, 0.f);
    o1.z = fmaxf(acc1.z * i1 + b1.z, 0.f); o1.w = fmaxf(acc1.w * i1 + b1.w, 0.f);
    *(float4*)(outb + (size_t)n * 256 + lane * 4) = o0;
    *(float4*)(outb + (size_t)n * 256 + 128 + lane * 4) = o1;
}

// ---------------- per-graph mean ----------------
__global__ void meanpart_kernel() {
    int g = blockIdx.x, s = blockIdx.y, inst = blockIdx.z, d = threadIdx.x;
    int beg = g_goff[inst * 65 + g], end = g_goff[inst * 65 + g + 1];
    const float* outb = g_tg + (size_t)inst * NN * 896;
    int cnt = end - beg;
    int chunk = (cnt + 15) / 16;
    int lo = beg + s * chunk;
    int hi = min(lo + chunk, end);
    float acc = 0.f;
    for (int r = lo; r < hi; r++) acc += outb[(size_t)r * 256 + d];
    g_part[((size_t)inst * 64 * 16 + g * 16 + s) * 256 + d] = acc;
}

__global__ void meanred_kernel() {
    int idx = blockIdx.x * 256 + threadIdx.x;
    int inst = blockIdx.y;
    if (idx >= 64 * 256) return;
    int g = idx >> 8;
    float acc = 0.f;
    for (int s = 0; s < 16; s++)
        acc += g_part[((size_t)inst * 64 * 16 + g * 16 + s) * 256 + (idx & 255)];
    float cnt = (float)(g_goff[inst * 65 + g + 1] - g_goff[inst * 65 + g]);
    g_hg[(size_t)inst * 64 * 256 + idx] = acc / fmaxf(cnt, 1.0f);
}

// ---------------- classifier ----------------
__global__ void classify_kernel(const float* __restrict__ Wc, const float* __restrict__ bc) {
    int idx = blockIdx.x * 256 + threadIdx.x;
    int inst = blockIdx.y;
    if (idx >= 64 * 2 * 32) return;
    int g = idx >> 6;
    int hh = (idx >> 5) & 1;
    int c = idx & 31;
    float s = bc[c];
    const float* hg = g_hg + (size_t)inst * 64 * 256 + g * 256 + hh * 128;
    const float* wr = Wc + c * 128;
    for (int d = 0; d < 128; d++) s += hg[d] * wr[d];
    g_logits[inst * 4096 + idx] = s;
}

// ---------------- combine ----------------
__global__ void combine_kernel(float* __restrict__ out) {
    int b = threadIdx.x;
    if (b >= 64) return;
    float dist[2];
    for (int hh = 0; hh < 2; hh++) {
        int base = b * 64 + hh * 32;
        float ss = 0.f;
        for (int c = 0; c < 32; c++) {
            float diff = g_logits[base + c] - g_logits[4096 + base + c] + 1e-6f;
            ss += diff * diff;
        }
        dist[hh] = sqrtf(ss);
    }
    float mx = fmaxf(dist[0], dist[1]);
    float e0 = expf(dist[0] - mx), e1 = expf(dist[1] - mx);
    float inv = 1.0f / (e0 + e1);
    out[b * 2 + 0] = e0 * inv;
    out[b * 2 + 1] = e1 * inv;
}

// ---------------- host ----------------
extern "C" void kernel_launch(void* const* d_in, const int* in_sizes, int n_in,
                              void* d_out, int out_size) {
    const float* f0 = (const float*)d_in[0];
    const float* f1 = (const float*)d_in[1];
    const int* src0 = (const int*)d_in[2];
    const int* dst0 = (const int*)d_in[3];
    const int* et0  = (const int*)d_in[4];
    const int* gid0 = (const int*)d_in[5];
    const int* src1 = (const int*)d_in[6];
    const int* dst1 = (const int*)d_in[7];
    const int* et1  = (const int*)d_in[8];
    const int* gid1 = (const int*)d_in[9];
    const float* W_et   = (const float*)d_in[10];
    const float* b_et   = (const float*)d_in[11];
    const float* W_ih   = (const float*)d_in[12];
    const float* W_hh   = (const float*)d_in[13];
    const float* b_ih   = (const float*)d_in[14];
    const float* b_hh   = (const float*)d_in[15];
    const float* W_fc   = (const float*)d_in[16];
    const float* attn_l = (const float*)d_in[17];
    const float* attn_r = (const float*)d_in[18];
    const float* gbias  = (const float*)d_in[19];
    const float* W_cls  = (const float*)d_in[20];
    const float* b_cls  = (const float*)d_in[21];

    float *p_tg, *p_gi, *p_zft, *p_btg, *p_zero;
    int *p_cursor;
    __nv_bfloat16 *p_cvhh, *p_cvhl, *p_cvah, *p_cval;
    __nv_bfloat16 *p_Wtgh, *p_Wtgl, *p_Wihh, *p_Wihl, *p_Wfch, *p_Wfcl;
    cudaGetSymbolAddress((void**)&p_tg, g_tg);
    cudaGetSymbolAddress((void**)&p_gi, g_gi);
    cudaGetSymbolAddress((void**)&p_zft, g_zft);
    cudaGetSymbolAddress((void**)&p_btg, g_btg);
    cudaGetSymbolAddress((void**)&p_zero, g_zerobias);
    cudaGetSymbolAddress((void**)&p_cursor, g_cursor);
    cudaGetSymbolAddress((void**)&p_cvhh, g_cvhh);
    cudaGetSymbolAddress((void**)&p_cvhl, g_cvhl);
    cudaGetSymbolAddress((void**)&p_cvah, g_cvah);
    cudaGetSymbolAddress((void**)&p_cval, g_cval);
    cudaGetSymbolAddress((void**)&p_Wtgh, g_Wtgh);
    cudaGetSymbolAddress((void**)&p_Wtgl, g_Wtgl);
    cudaGetSymbolAddress((void**)&p_Wihh, g_Wihh);
    cudaGetSymbolAddress((void**)&p_Wihl, g_Wihl);
    cudaGetSymbolAddress((void**)&p_Wfch, g_Wfch);
    cudaGetSymbolAddress((void**)&p_Wfcl, g_Wfcl);

    cudaFuncSetAttribute(gemm_mma, cudaFuncAttributeMaxDynamicSharedMemorySize, SMEM_GEMM_BYTES);

    const int EB = (EE + 255) / 256;

    // 1-4: weight conversions (W_et||W_hh concatenated into Wtg)
    conv_split<<<(512 * 128 + 255) / 256, 256>>>(W_et, p_Wtgh, p_Wtgl, 512 * 128);
    conv_split<<<(384 * 128 + 255) / 256, 256>>>(W_hh, p_Wtgh + 512 * 128, p_Wtgl + 512 * 128, 384 * 128);
    conv_split<<<(384 * 128 + 255) / 256, 256>>>(W_ih, p_Wihh, p_Wihl, 384 * 128);
    conv_split<<<(256 * 128 + 255) / 256, 256>>>(W_fc, p_Wfch, p_Wfcl, 256 * 128);
    // 5: prep h (both instances) + bias concat
    prep_kernel<<<(2 * NN * 128 + 255) / 256, 256>>>(f0, f1, b_et, b_hh);
    // 6: first combined [t|gh] GEMM (profiled by ncu -s 5)
    gemm_mma<<<dim3(14, 391, 2), 256, SMEM_GEMM_BYTES>>>(
        p_cvhh, p_cvhl, p_Wtgh, p_Wtgl, p_btg, p_tg, 896, (size_t)NN * 896);
    // CSR build (overlap-free but batched)
    cudaMemsetAsync(p_cursor, 0, 2 * NI * sizeof(int), 0);
    hist_kernel<<<dim3(EB, 2), 256>>>(dst0, dst1);
    scan_kernel<<<2, 1024>>>();
    scatter_kernel<<<dim3(EB, 2), 256>>>(dst0, dst1);
    goff_kernel<<<2, 65>>>(gid0, gid1);

    for (int step = 0; step < NSTEPS; step++) {
        if (step > 0)
            gemm_mma<<<dim3(14, 391, 2), 256, SMEM_GEMM_BYTES>>>(
                p_cvhh, p_cvhl, p_Wtgh, p_Wtgl, p_btg, p_tg, 896, (size_t)NN * 896);
        aggregate_kernel<<<dim3(6250, 2), 256>>>(src0, src1, et0, et1);
        gemm_mma<<<dim3(6, 391, 2), 256, SMEM_GEMM_BYTES>>>(
            p_cvah, p_cval, p_Wihh, p_Wihl, b_ih, p_gi, 384, (size_t)NN * 384);
        gru_kernel<<<(2 * NN * 128 + 255) / 256, 256>>>();
    }

    normsig_kernel<<<12500, 256>>>();
    gemm_mma<<<dim3(4, 391, 2), 256, SMEM_GEMM_BYTES>>>(
        p_cvhh, p_cvhl, p_Wfch, p_Wfcl, p_zero, p_zft, 256, (size_t)NN * 256);
    elr_kernel<<<12500, 256>>>(attn_l, attn_r);
    gatmax_kernel<<<dim3((NN + 255) / 256, 2), 256>>>(src0, src1);
    gatagg_kernel<<<dim3(6250, 2), 256>>>(src0, src1, gbias);
    meanpart_kernel<<<dim3(64, 16, 2), 256>>>();
    meanred_kernel<<<dim3(64, 2), 256>>>();
    classify_kernel<<<dim3(16, 2), 256>>>(W_cls, b_cls);
    combine_kernel<<<1, 64>>>((float*)d_out);
}